// round 17
// baseline (speedup 1.0000x reference)
#include <cuda_runtime.h>
#include <cuda_fp16.h>
#include <math.h>
#include <stdint.h>

#define HQn 16
#define HKn 4
#define Dn 64
#define GATE_CHn 12
#define WINDOWn 1024
#define Bn 2
#define Tn 2048
#define En 1024
#define Fn 1536
#define Mn 4096

// Scratch (allocation-free rule: device globals). All fp16 data stored as
// uint32_t words (half2 pairs).
__device__ __align__(256) uint32_t g_att[(size_t)Mn * En / 2];
__device__ __align__(256) uint32_t g_xh[(size_t)Mn * En / 2];
__device__ __align__(256) uint32_t g_wqh[(size_t)Fn * En / 2];
__device__ __align__(256) uint32_t g_woh[(size_t)En * En / 2];
__device__ __align__(256) uint32_t g_qpack[(size_t)Bn * HQn * Tn * 32];
__device__ __align__(256) uint32_t g_kpack[(size_t)Bn * HKn * Tn * 32];
__device__ __align__(256) uint32_t g_vpack[(size_t)Bn * HKn * Dn * Tn / 2]; // [b][hk][d][t/2]

// ---------------------------------------------------------------------------
// helpers
// ---------------------------------------------------------------------------
__device__ __forceinline__ uint32_t pack2(float lo, float hi) {
    __half2 h = __floats2half2_rn(lo, hi);
    return *(uint32_t*)&h;
}

__device__ __forceinline__ void mma_f16(float* d, const uint32_t* a,
                                        const uint32_t* b) {
    asm volatile(
        "mma.sync.aligned.m16n8k16.row.col.f32.f16.f16.f32 "
        "{%0,%1,%2,%3}, {%4,%5,%6,%7}, {%8,%9}, {%0,%1,%2,%3};\n"
        : "+f"(d[0]), "+f"(d[1]), "+f"(d[2]), "+f"(d[3])
        : "r"(a[0]), "r"(a[1]), "r"(a[2]), "r"(a[3]), "r"(b[0]), "r"(b[1]));
}

__device__ __forceinline__ uint32_t sma(const void* p) {
    return (uint32_t)__cvta_generic_to_shared(p);
}
__device__ __forceinline__ void cp16(uint32_t dst, const void* src) {
    asm volatile("cp.async.cg.shared.global [%0], [%1], 16;\n"
                 :: "r"(dst), "l"(src));
}
__device__ __forceinline__ void cp_commit() {
    asm volatile("cp.async.commit_group;\n");
}
template <int N>
__device__ __forceinline__ void cp_wait() {
    asm volatile("cp.async.wait_group %0;\n" :: "n"(N));
}

// ---------------------------------------------------------------------------
// Prepass: fp32 -> fp16 (rn), packed half2 words, canonical order.
// ---------------------------------------------------------------------------
__global__ void cvt_h(const float* __restrict__ src,
                      uint32_t* __restrict__ dst, int n4)
{
    const int i = blockIdx.x * blockDim.x + threadIdx.x;
    if (i < n4) {
        float4 v = ((const float4*)src)[i];
        uint2 o;
        o.x = pack2(v.x, v.y);
        o.y = pack2(v.z, v.w);
        ((uint2*)dst)[i] = o;
    }
}

// ---------------------------------------------------------------------------
// FP16 GEMM: C[M,N] = A[M,K] * B[N,K]^T (fp16 half2-word inputs).
// 128x128 tile, BK=64 (4 x m16n8k16 k-chunks per iter: halved barrier
// count vs BK=32), 8 warps (32m x 64n), cp.async double-buffered,
// smem row stride 36 words (32 data + 4 pad, conflict-free), 2 CTAs/SM.
// FUSED: each warp's 64 cols == one head; epilogue applies gate/RoPE/RMS
// and writes fp16 attention packs directly.
// ---------------------------------------------------------------------------
#define GW 36
#define GA_W (128 * GW)
#define GSTG_W (2 * GA_W)
#define GEMM_SMEM_BYTES (2 * GSTG_W * 4)

template <bool FUSED>
__global__ __launch_bounds__(256, 2) void gemm_f16(
    const uint32_t* __restrict__ A, const uint32_t* __restrict__ Bm,
    float* __restrict__ C, int M, int N, int K,
    const float* __restrict__ x, const float* __restrict__ ve,
    const float* __restrict__ rc, const float* __restrict__ rs,
    const float* __restrict__ wg, uint32_t* __restrict__ qp,
    uint32_t* __restrict__ kpck, uint32_t* __restrict__ vpck)
{
    extern __shared__ uint32_t gsm[];

    const int tid = threadIdx.x;
    const int lane = tid & 31;
    const int warp = tid >> 5;
    const int wm = (warp & 3) * 32;
    const int wn = (warp >> 2) * 64;
    const int bm = blockIdx.y * 128;
    const int bn = blockIdx.x * 128;
    const int lq = lane >> 2;
    const int lc = lane & 3;
    const int Kw = K >> 1;           // words per gmem row

    float acc[2][8][4];
    #pragma unroll
    for (int mt = 0; mt < 2; mt++)
        #pragma unroll
        for (int nt = 0; nt < 8; nt++)
            #pragma unroll
            for (int i = 0; i < 4; i++) acc[mt][nt][i] = 0.f;

    auto pref = [&](int b, int kc) {       // kc = BK64-chunk index
        uint32_t* Ad = gsm + b * GSTG_W;
        uint32_t* Bd = Ad + GA_W;
        const int k0w = kc * 32;
        #pragma unroll
        for (int i = 0; i < 4; i++) {
            const int g = tid + 256 * i;
            const int row = g >> 3;
            const int c4 = (g & 7) * 4;
            cp16(sma(Ad + row * GW + c4), A + (size_t)(bm + row) * Kw + k0w + c4);
            cp16(sma(Bd + row * GW + c4), Bm + (size_t)(bn + row) * Kw + k0w + c4);
        }
    };

    const int niter = K / 64;
    pref(0, 0);
    cp_commit();

    for (int ki = 0; ki < niter; ki++) {
        if (ki + 1 < niter) {
            pref((ki + 1) & 1, ki + 1);
            cp_commit();
            cp_wait<1>();
        } else {
            cp_wait<0>();
        }
        __syncthreads();

        const uint32_t* Ac = gsm + (ki & 1) * GSTG_W;
        const uint32_t* Bc = Ac + GA_W;

        // A fragments: [mt][chunk][4] (rows lq, lq+8 of each m16 tile)
        uint32_t af[2][4][4];
        #pragma unroll
        for (int mt = 0; mt < 2; mt++) {
            const uint32_t* p0 = Ac + (wm + mt * 16 + lq) * GW;
            const uint32_t* p1 = p0 + 8 * GW;
            #pragma unroll
            for (int c = 0; c < 4; c++) {
                af[mt][c][0] = p0[8 * c + lc];
                af[mt][c][1] = p1[8 * c + lc];
                af[mt][c][2] = p0[8 * c + lc + 4];
                af[mt][c][3] = p1[8 * c + lc + 4];
            }
        }

        #pragma unroll
        for (int nt = 0; nt < 8; nt++) {
            const uint32_t* pb = Bc + (wn + nt * 8 + lq) * GW;
            uint32_t bw[4][2];
            #pragma unroll
            for (int c = 0; c < 4; c++) {
                bw[c][0] = pb[8 * c + lc];
                bw[c][1] = pb[8 * c + lc + 4];
            }
            #pragma unroll
            for (int c = 0; c < 4; c++) {
                mma_f16(acc[0][nt], af[0][c], bw[c]);
                mma_f16(acc[1][nt], af[1][c], bw[c]);
            }
        }
        __syncthreads();
    }

    if (!FUSED) {
        #pragma unroll
        for (int mt = 0; mt < 2; mt++) {
            const int r0 = bm + wm + mt * 16 + lq;
            #pragma unroll
            for (int nt = 0; nt < 8; nt++) {
                const int c0 = bn + wn + nt * 8 + 2 * lc;
                *(float2*)(C + (size_t)r0 * N + c0) =
                    make_float2(acc[mt][nt][0], acc[mt][nt][1]);
                *(float2*)(C + (size_t)(r0 + 8) * N + c0) =
                    make_float2(acc[mt][nt][2], acc[mt][nt][3]);
            }
        }
        return;
    }

    // ---- fused epilogue: warp's 64 columns == one head
    const int head = (bn + wn) >> 6;
    if (head < HQn + HKn) {
        #pragma unroll
        for (int mt = 0; mt < 2; mt++) {
            #pragma unroll
            for (int rowh = 0; rowh < 2; rowh++) {
                const int r = bm + wm + mt * 16 + lq + 8 * rowh;
                const int t = r & (Tn - 1);
                const int b = r >> 11;
                float yl[4][2], yh[4][2];
                float ss = 0.f;
                #pragma unroll
                for (int nt = 0; nt < 4; nt++)
                    #pragma unroll
                    for (int e = 0; e < 2; e++) {
                        const int d = nt * 8 + 2 * lc + e;
                        const float cv = rc[t * 32 + d];
                        const float sv = rs[t * 32 + d];
                        const float alo = acc[mt][nt][2 * rowh + e];
                        const float ahi = acc[mt][nt + 4][2 * rowh + e];
                        const float y1 = alo * cv - ahi * sv;
                        const float y2 = alo * sv + ahi * cv;
                        yl[nt][e] = y1; yh[nt][e] = y2;
                        ss += y1 * y1 + y2 * y2;
                    }
                ss += __shfl_xor_sync(0xffffffffu, ss, 1);
                ss += __shfl_xor_sync(0xffffffffu, ss, 2);
                const float rr = rsqrtf(ss * (1.0f / Dn) + 1e-8f);
                if (head < HQn) {
                    uint32_t* qw = qp + ((size_t)(b * HQn + head) * Tn + t) * 32;
                    const float sc = rr * 0.125f;
                    #pragma unroll
                    for (int nt = 0; nt < 4; nt++) {
                        qw[nt * 4 + lc] =
                            pack2(yl[nt][0] * sc, yl[nt][1] * sc);
                        qw[16 + nt * 4 + lc] =
                            pack2(yh[nt][0] * sc, yh[nt][1] * sc);
                    }
                } else {
                    const int hk = head - HQn;
                    uint32_t* kw = kpck +
                        ((size_t)(b * HKn + hk) * Tn + t) * 32;
                    #pragma unroll
                    for (int nt = 0; nt < 4; nt++) {
                        kw[nt * 4 + lc] =
                            pack2(yl[nt][0] * rr, yl[nt][1] * rr);
                        kw[16 + nt * 4 + lc] =
                            pack2(yh[nt][0] * rr, yh[nt][1] * rr);
                    }
                }
            }
        }
    } else {
        // v head: gate mix + transposed fp16 pack ([d][t])
        const int hv = head - HQn - HKn;
        #pragma unroll
        for (int mt = 0; mt < 2; mt++) {
            #pragma unroll
            for (int rowh = 0; rowh < 2; rowh++) {
                const int r = bm + wm + mt * 16 + lq + 8 * rowh;
                const int t = r & (Tn - 1);
                const int b = r >> 11;
                float pr = 0.f;
                #pragma unroll
                for (int j = 0; j < 3; j++) {
                    const int c = lc + 4 * j;
                    pr += x[(size_t)r * En + c] * wg[hv * GATE_CHn + c];
                }
                pr += __shfl_xor_sync(0xffffffffu, pr, 1);
                pr += __shfl_xor_sync(0xffffffffu, pr, 2);
                const float gate = 3.0f / (1.0f + __expf(-pr));
                __half* vh = (__half*)(vpck +
                    (size_t)(b * HKn + hv) * Dn * (Tn / 2));
                const float* vep = ve + (size_t)r * (HKn * Dn) + hv * Dn;
                #pragma unroll
                for (int nt = 0; nt < 8; nt++)
                    #pragma unroll
                    for (int e = 0; e < 2; e++) {
                        const int d = nt * 8 + 2 * lc + e;
                        vh[(size_t)d * Tn + t] = __float2half(
                            acc[mt][nt][2 * rowh + e] + gate * vep[d]);
                    }
            }
        }
    }
}

// ---------------------------------------------------------------------------
// FP16 tensor-core flash attention: m16n8k16, KTILE=64, cp.async double-
// buffered K (rows [64][36w]) and V-transposed (rows d [64][36w]),
// fixed-max softmax, Ps half2 [128][36w], interior-tile mask skip.
// Output fp16 packed (consumed by gemm_f16<false>).
// ---------------------------------------------------------------------------
#define KT 64
#define KWs 36
#define AKW (64 * KWs)
#define ABW (2 * AKW)
#define W_PSa (2 * ABW)
#define ATTN_WORDS (W_PSa + 128 * 36)
#define ATTN_SMEM_BYTES (ATTN_WORDS * 4)

__global__ __launch_bounds__(256, 2) void attn_f16(
    const uint32_t* __restrict__ qpack, const uint32_t* __restrict__ kpack,
    const uint32_t* __restrict__ vpack, uint32_t* __restrict__ outw)
{
    extern __shared__ uint32_t smu[];
    uint32_t* Ps = smu + W_PSa;

    const int tid = threadIdx.x;
    const int lane = tid & 31;
    const int warp = tid >> 5;
    const int q0 = blockIdx.x * 128;
    const int h  = blockIdx.y;
    const int bb = blockIdx.z;
    const int hk = h >> 2;
    const int row0 = bb * Tn + q0;

    const int lq = lane >> 2;
    const int lc = lane & 3;
    const int rA = warp * 16 + lq;

    const uint32_t* kpb = kpack + (size_t)(bb * HKn + hk) * Tn * 32;
    const uint32_t* vpb = vpack + (size_t)(bb * HKn + hk) * Dn * (Tn / 2);

    // Q fragments (fp16, pre-scaled by 1/8): [chunk][4]
    uint32_t qf[4][4];
    {
        const uint32_t* q0p = qpack +
            ((size_t)(bb * HQn + h) * Tn + q0 + rA) * 32;
        const uint32_t* q1p = q0p + 8 * 32;
        #pragma unroll
        for (int c = 0; c < 4; c++) {
            qf[c][0] = q0p[8 * c + lc];
            qf[c][1] = q1p[8 * c + lc];
            qf[c][2] = q0p[8 * c + lc + 4];
            qf[c][3] = q1p[8 * c + lc + 4];
        }
    }

    float o[8][4];
    #pragma unroll
    for (int nt = 0; nt < 8; nt++)
        #pragma unroll
        for (int e = 0; e < 4; e++) o[nt][e] = 0.f;
    float lA = 0.f, lB = 0.f;

    const int kt_lo = (q0 > WINDOWn) ? ((q0 - WINDOWn) >> 6) : 0;
    const int kt_hi = (q0 + 127) >> 6;

    auto pref = [&](int bidx, int kt) {
        uint32_t* Kd = smu + bidx * ABW;
        uint32_t* Vd = Kd + AKW;
        #pragma unroll
        for (int i = 0; i < 4; i++) {
            const int g = tid + 256 * i;
            const int reg = g >> 9;
            const int idx = g & 511;
            const int row = idx >> 3;
            const int c4 = (idx & 7) * 4;
            if (reg == 0)
                cp16(sma(Kd + row * KWs + c4),
                     kpb + (size_t)(kt * 64 + row) * 32 + c4);
            else
                cp16(sma(Vd + row * KWs + c4),
                     vpb + (size_t)row * (Tn / 2) + kt * 32 + c4);
        }
    };

    pref(0, kt_lo);
    cp_commit();

    for (int kt = kt_lo; kt <= kt_hi; kt++) {
        const int cur = (kt - kt_lo) & 1;
        if (kt < kt_hi) {
            pref(cur ^ 1, kt + 1);
            cp_commit();
            cp_wait<1>();
        } else {
            cp_wait<0>();
        }
        __syncthreads();

        const uint32_t* Kc = smu + cur * ABW;
        const uint32_t* Vc = Kc + AKW;
        const int k0 = kt * KT;
        const bool full_live = (k0 + KT - 1 <= q0) &&
                               (k0 >= q0 + 127 - WINDOWn);

        // ---- S = Q K^T + softmax + P store
        #pragma unroll
        for (int nt = 0; nt < 8; nt++) {
            const uint32_t* kw = Kc + (nt * 8 + lq) * KWs;
            float s0[4] = {0.f, 0.f, 0.f, 0.f};
            float s1[4] = {0.f, 0.f, 0.f, 0.f};
            #pragma unroll
            for (int c = 0; c < 4; c++) {
                uint32_t bf[2] = {kw[8 * c + lc], kw[8 * c + lc + 4]};
                mma_f16((c & 1) ? s1 : s0, qf[c], bf);
            }

            float p[4];
            if (full_live) {
                #pragma unroll
                for (int e = 0; e < 4; e++)
                    p[e] = __expf((s0[e] + s1[e]) - 8.0f);
            } else {
                #pragma unroll
                for (int e = 0; e < 4; e++) {
                    const float sv = s0[e] + s1[e];
                    const int i = q0 + rA + ((e >= 2) ? 8 : 0);
                    const int j = k0 + nt * 8 + 2 * lc + (e & 1);
                    const bool live = (j <= i) && (j + WINDOWn >= i);
                    p[e] = live ? __expf(sv - 8.0f) : 0.f;
                }
            }
            lA += p[0] + p[1];
            lB += p[2] + p[3];

            Ps[rA * 36 + nt * 4 + lc] = pack2(p[0], p[1]);
            Ps[(rA + 8) * 36 + nt * 4 + lc] = pack2(p[2], p[3]);
        }
        __syncwarp();   // own-warp P rows only

        // ---- O += P V  (c-outer for o reuse distance 8)
        uint32_t pa[4][4];
        {
            const uint32_t* p0 = Ps + rA * 36;
            const uint32_t* p1 = Ps + (rA + 8) * 36;
            #pragma unroll
            for (int c = 0; c < 4; c++) {
                pa[c][0] = p0[8 * c + lc];
                pa[c][1] = p1[8 * c + lc];
                pa[c][2] = p0[8 * c + lc + 4];
                pa[c][3] = p1[8 * c + lc + 4];
            }
        }
        #pragma unroll
        for (int c = 0; c < 4; c++) {
            #pragma unroll
            for (int nt = 0; nt < 8; nt++) {
                const uint32_t* vw = Vc + (nt * 8 + lq) * KWs;
                uint32_t bf[2] = {vw[8 * c + lc], vw[8 * c + lc + 4]};
                mma_f16(o[nt], pa[c], bf);
            }
        }
        __syncthreads();   // cur fully consumed before next pref overwrites
    }

    lA += __shfl_xor_sync(0xffffffffu, lA, 1);
    lA += __shfl_xor_sync(0xffffffffu, lA, 2);
    lB += __shfl_xor_sync(0xffffffffu, lB, 1);
    lB += __shfl_xor_sync(0xffffffffu, lB, 2);
    const float invA = 1.0f / lA;
    const float invB = 1.0f / lB;

    // fp16 packed output (row stride En/2 words)
    #pragma unroll
    for (int nt = 0; nt < 8; nt++) {
        const int cw = h * 32 + nt * 4 + lc;
        outw[(size_t)(row0 + rA) * (En / 2) + cw] =
            pack2(o[nt][0] * invA, o[nt][1] * invA);
        outw[(size_t)(row0 + rA + 8) * (En / 2) + cw] =
            pack2(o[nt][2] * invB, o[nt][3] * invB);
    }
}

// ---------------------------------------------------------------------------
extern "C" void kernel_launch(void* const* d_in, const int* in_sizes, int n_in,
                              void* d_out, int out_size)
{
    (void)in_sizes; (void)n_in; (void)out_size;
    const float* x    = (const float*)d_in[0];
    const float* ve   = (const float*)d_in[1];
    const float* rc   = (const float*)d_in[2];
    const float* rs   = (const float*)d_in[3];
    const float* wqkv = (const float*)d_in[4];
    const float* wg   = (const float*)d_in[5];
    const float* wo   = (const float*)d_in[6];
    float* out = (float*)d_out;

    uint32_t *att_p, *qp, *kp, *vp, *xh, *wqh, *woh;
    cudaGetSymbolAddress((void**)&att_p, g_att);
    cudaGetSymbolAddress((void**)&qp, g_qpack);
    cudaGetSymbolAddress((void**)&kp, g_kpack);
    cudaGetSymbolAddress((void**)&vp, g_vpack);
    cudaGetSymbolAddress((void**)&xh, g_xh);
    cudaGetSymbolAddress((void**)&wqh, g_wqh);
    cudaGetSymbolAddress((void**)&woh, g_woh);

    cudaFuncSetAttribute(gemm_f16<true>,
                         cudaFuncAttributeMaxDynamicSharedMemorySize,
                         GEMM_SMEM_BYTES);
    cudaFuncSetAttribute(gemm_f16<false>,
                         cudaFuncAttributeMaxDynamicSharedMemorySize,
                         GEMM_SMEM_BYTES);
    cudaFuncSetAttribute(attn_f16,
                         cudaFuncAttributeMaxDynamicSharedMemorySize,
                         ATTN_SMEM_BYTES);

    cvt_h<<<(Mn * En / 4 + 255) / 256, 256>>>(x, xh, Mn * En / 4);
    cvt_h<<<(Fn * En / 4 + 255) / 256, 256>>>(wqkv, wqh, Fn * En / 4);
    cvt_h<<<(En * En / 4 + 255) / 256, 256>>>(wo, woh, En * En / 4);

    // qkv projection with fused gate/RoPE/RMS/pack epilogue
    gemm_f16<true><<<dim3(Fn / 128, Mn / 128), 256, GEMM_SMEM_BYTES>>>(
        xh, wqh, nullptr, Mn, Fn, En, x, ve, rc, rs, wg, qp, kp, vp);
    attn_f16<<<dim3(Tn / 128, HQn, Bn), 256, ATTN_SMEM_BYTES>>>(
        qp, kp, vp, att_p);
    gemm_f16<false><<<dim3(En / 128, Mn / 128), 256, GEMM_SMEM_BYTES>>>(
        att_p, woh, out, Mn, En, En,
        nullptr, nullptr, nullptr, nullptr, nullptr, nullptr, nullptr, nullptr);
}